// round 15
// baseline (speedup 1.0000x reference)
#include <cuda_runtime.h>
#include <cstdint>

// Problem-fixed sizes (GraphNet_57432302682564): N=150000, E=4800000
// Affine-factored 3-layer SAGE: full-graph work only for A*h0 at bm1 rows
// (~38% edge coverage); A^2*h0 via stored edge list L2 (~72k edges); output
// combine via four [8,3] matrices. Normalization deferred to read sites.
#define NN    150000
#define NPAD  150016
#define EE    4800000
#define NOUT  68
#define BMW   (NPAD / 32)
#define EPT   16            // edges per thread in streaming scans (4x int4 -> MLP 4)

// ---------------- scratch (device globals; no allocation allowed) ----------------
__device__ float4 g_P0[NPAD * 2];    // h0 = [x | tanh(pos)]
__device__ float4 g_S1[NPAD * 2];    // unnormalized sum P0[src] at bm1 rows
__device__ float4 g_S2[NPAD * 2];    // sum of (S1[src]/cnt[src]) at bm2 rows
__device__ int    g_cnt[NPAD];       // in-degree at bm1 rows
__device__ float  g_S3[NOUT * 12];   // out rows: 8ch sum P2[src]; ch8 sum u[src]
__device__ unsigned int g_list[EE];          // edges with dst<NOUT: (dst<<25)|src
__device__ unsigned long long g_list2[EE];   // edges with dst in bm2: (dst<<32)|src
__device__ int    g_nlist  = 0;      // static init for run 1; k_final resets
__device__ int    g_nlist2 = 0;
__device__ unsigned int g_bm1[BMW];  // rows needing S1/cnt
__device__ unsigned int g_bm2[BMW];  // rows needing S2

// ---------------- helpers ----------------
__device__ __forceinline__ void red_v4(float* addr, float a, float b, float c, float d) {
    asm volatile("red.global.add.v4.f32 [%0], {%1,%2,%3,%4};"
                 :: "l"(addr), "f"(a), "f"(b), "f"(c), "f"(d)
                 : "memory");
}
__device__ __forceinline__ void red_s32(int* addr, int v) {
    asm volatile("red.global.add.s32 [%0], %1;" :: "l"(addr), "r"(v) : "memory");
}
__device__ __forceinline__ bool bit_test(const unsigned int* bm, int i) {
    return (bm[i >> 5] >> (i & 31)) & 1u;
}

// ---------------- K0: build P0, zero bitmaps/S3, scan1 (collect dst<NOUT edges) ----
__global__ void k_init_scan1(const float* __restrict__ x,
                             const float* __restrict__ wpos,
                             const float* __restrict__ bpos,
                             const int* __restrict__ srcs,
                             const int* __restrict__ dsts,
                             int n, int e)
{
    int t = blockIdx.x * blockDim.x + threadIdx.x;
    if (t < n) {
        float fi = (float)t;
        float4 a, b;
        a.x = x[t * 3 + 0];
        a.y = x[t * 3 + 1];
        a.z = x[t * 3 + 2];
        a.w = tanhf(fi * wpos[0] + bpos[0]);
        b.x = tanhf(fi * wpos[1] + bpos[1]);
        b.y = tanhf(fi * wpos[2] + bpos[2]);
        b.z = tanhf(fi * wpos[3] + bpos[3]);
        b.w = tanhf(fi * wpos[4] + bpos[4]);
        g_P0[t * 2]     = a;
        g_P0[t * 2 + 1] = b;
    }
    if (t < NOUT * 12) g_S3[t] = 0.f;
    if (t < BMW) { g_bm1[t] = 0u; g_bm2[t] = 0u; }

    // scan1: dst stream only; hits are rare (~1 in 2200)
    int base = t * EPT;
    bool vecok = ((e & 3) == 0);
    if (vecok && base + EPT <= e) {
        #pragma unroll
        for (int g = 0; g < EPT / 4; g++) {
            int4 d4 = *(const int4*)(dsts + base + 4 * g);
            int dd[4] = {d4.x, d4.y, d4.z, d4.w};
            #pragma unroll
            for (int j = 0; j < 4; j++) {
                if (dd[j] < NOUT) {
                    int s = srcs[base + 4 * g + j];
                    int idx = atomicAdd(&g_nlist, 1);
                    if (idx < EE)
                        g_list[idx] = ((unsigned)dd[j] << 25) | (unsigned)s;
                }
            }
        }
    } else {
        for (int k = base; k < e && k < base + EPT; k++) {
            int d = dsts[k];
            if (d < NOUT) {
                int s = srcs[k];
                int idx = atomicAdd(&g_nlist, 1);
                if (idx < EE)
                    g_list[idx] = ((unsigned)d << 25) | (unsigned)s;
            }
        }
    }
}

// ---------------- M2: bm2 (+bm1) = list1 sources + rows<NOUT; zero their rows ----
__global__ void k_mark2()
{
    int t = blockIdx.x * blockDim.x + threadIdx.x;
    int stride = gridDim.x * blockDim.x;
    float4 z = make_float4(0.f, 0.f, 0.f, 0.f);
    if (t < NOUT) {
        atomicOr(&g_bm2[t >> 5], 1u << (t & 31));
        atomicOr(&g_bm1[t >> 5], 1u << (t & 31));
        g_S1[t * 2] = z; g_S1[t * 2 + 1] = z;
        g_S2[t * 2] = z; g_S2[t * 2 + 1] = z;
        g_cnt[t] = 0;
    }
    int nl = g_nlist; if (nl > EE) nl = EE;
    for (int i = t; i < nl; i += stride) {
        int s = (int)(g_list[i] & 0x1FFFFFFu);
        atomicOr(&g_bm2[s >> 5], 1u << (s & 31));
        atomicOr(&g_bm1[s >> 5], 1u << (s & 31));
        g_S1[s * 2] = z; g_S1[s * 2 + 1] = z;   // idempotent zero; races benign
        g_S2[s * 2] = z; g_S2[s * 2 + 1] = z;
        g_cnt[s] = 0;
    }
}

// ---------------- S2: scan dst stream, collect edges into bm2 as L2 list ----------
__global__ void k_scan2(const int* __restrict__ srcs, const int* __restrict__ dsts, int e)
{
    int t = blockIdx.x * blockDim.x + threadIdx.x;
    int base = t * EPT;
    bool vecok = ((e & 3) == 0);
    if (vecok && base + EPT <= e) {
        #pragma unroll
        for (int g = 0; g < EPT / 4; g++) {
            int4 d4 = *(const int4*)(dsts + base + 4 * g);
            int dd[4] = {d4.x, d4.y, d4.z, d4.w};
            #pragma unroll
            for (int j = 0; j < 4; j++) {
                if (bit_test(g_bm2, dd[j])) {          // ~1.5% hit
                    int s = srcs[base + 4 * g + j];
                    int idx = atomicAdd(&g_nlist2, 1);
                    if (idx < EE)
                        g_list2[idx] = ((unsigned long long)(unsigned)dd[j] << 32)
                                       | (unsigned)s;
                }
            }
        }
    } else {
        for (int k = base; k < e && k < base + EPT; k++) {
            int d = dsts[k];
            if (bit_test(g_bm2, d)) {
                int s = srcs[k];
                int idx = atomicAdd(&g_nlist2, 1);
                if (idx < EE)
                    g_list2[idx] = ((unsigned long long)(unsigned)d << 32)
                                   | (unsigned)s;
            }
        }
    }
}

// ---------------- M1: mark bm1 from L2 sources; zero their S1/cnt rows ----------
__global__ void k_mark1()
{
    int t = blockIdx.x * blockDim.x + threadIdx.x;
    int stride = gridDim.x * blockDim.x;
    float4 z = make_float4(0.f, 0.f, 0.f, 0.f);
    int nl2 = g_nlist2; if (nl2 > EE) nl2 = EE;
    for (int i = t; i < nl2; i += stride) {
        int s = (int)(g_list2[i] & 0xFFFFFFFFull);
        atomicOr(&g_bm1[s >> 5], 1u << (s & 31));
        g_S1[s * 2] = z; g_S1[s * 2 + 1] = z;   // idempotent; benign races
        g_cnt[s] = 0;
    }
}

// ---------------- S3: edge pass 1, bm1-filtered (aggregate P0 + degrees) ----------
__global__ void k_scan3(const int* __restrict__ srcs, const int* __restrict__ dsts, int e)
{
    int t = blockIdx.x * blockDim.x + threadIdx.x;
    int base = t * EPT;
    bool vecok = ((e & 3) == 0);
    if (vecok && base + EPT <= e) {
        int dd[EPT];
        #pragma unroll
        for (int g = 0; g < EPT / 4; g++) {
            int4 d4 = *(const int4*)(dsts + base + 4 * g);
            dd[4*g] = d4.x; dd[4*g+1] = d4.y; dd[4*g+2] = d4.z; dd[4*g+3] = d4.w;
        }
        unsigned hit = 0;
        #pragma unroll
        for (int k = 0; k < EPT; k++)
            hit |= (unsigned)bit_test(g_bm1, dd[k]) << k;
        if (hit == 0) return;
        #pragma unroll
        for (int g = 0; g < EPT / 4; g++) {
            unsigned gh = (hit >> (4 * g)) & 0xFu;
            if (gh == 0) continue;
            int4 s4 = *(const int4*)(srcs + base + 4 * g);
            int ss[4] = {s4.x, s4.y, s4.z, s4.w};
            #pragma unroll
            for (int j = 0; j < 4; j++) {
                if ((gh >> j) & 1u) {
                    int d = dd[4 * g + j];
                    float4 a = g_P0[ss[j] * 2];
                    float4 b = g_P0[ss[j] * 2 + 1];
                    float* dp = (float*)&g_S1[d * 2];
                    red_v4(dp,     a.x, a.y, a.z, a.w);
                    red_v4(dp + 4, b.x, b.y, b.z, b.w);
                    red_s32(&g_cnt[d], 1);
                }
            }
        }
    } else {
        for (int k = base; k < e && k < base + EPT; k++) {
            int d = dsts[k];
            if (!bit_test(g_bm1, d)) continue;
            int s = srcs[k];
            float4 a = g_P0[s * 2];
            float4 b = g_P0[s * 2 + 1];
            float* dp = (float*)&g_S1[d * 2];
            red_v4(dp,     a.x, a.y, a.z, a.w);
            red_v4(dp + 4, b.x, b.y, b.z, b.w);
            red_s32(&g_cnt[d], 1);
        }
    }
}

// ---------------- A2: aggregate S2 from stored L2 list (normalize src on the fly) --
__global__ void k_agg2()
{
    int t = blockIdx.x * blockDim.x + threadIdx.x;
    int stride = gridDim.x * blockDim.x;
    int nl2 = g_nlist2; if (nl2 > EE) nl2 = EE;
    for (int i = t; i < nl2; i += stride) {
        unsigned long long p = g_list2[i];
        int s = (int)(p & 0xFFFFFFFFull);
        int d = (int)(p >> 32);
        int c = g_cnt[s];
        float inv = 1.f / (float)(c > 1 ? c : 1);
        float4 a = g_S1[s * 2], b = g_S1[s * 2 + 1];
        float* dp = (float*)&g_S2[d * 2];
        red_v4(dp,     a.x * inv, a.y * inv, a.z * inv, a.w * inv);
        red_v4(dp + 4, b.x * inv, b.y * inv, b.z * inv, b.w * inv);
    }
}

// ---------------- K4: small pass (dst<NOUT): aggregate P2=S2/cnt and u-sums -------
__global__ void k_small()
{
    int nl = g_nlist; if (nl > EE) nl = EE;
    for (int t = blockIdx.x * blockDim.x + threadIdx.x; t < nl;
         t += gridDim.x * blockDim.x) {
        unsigned p = g_list[t];
        int s = (int)(p & 0x1FFFFFFu);
        int d = (int)(p >> 25);
        int c = g_cnt[s];                 // s in bm2 ⊆ bm1
        float inv = 1.f / (float)(c > 1 ? c : 1);
        float u = (c > 0) ? 1.f : 0.f;
        float4 a = g_S2[s * 2], b = g_S2[s * 2 + 1];
        float* dp = &g_S3[d * 12];
        red_v4(dp,     a.x * inv, a.y * inv, a.z * inv, a.w * inv);
        red_v4(dp + 4, b.x * inv, b.y * inv, b.z * inv, b.w * inv);
        atomicAdd(dp + 8, u);
    }
}

// ---------------- K5: combine matrices + final 68x3 output; reset counters --------
__global__ void k_final(const float* __restrict__ Wl1, const float* __restrict__ Wr1,
                        const float* __restrict__ b1,
                        const float* __restrict__ Wl2, const float* __restrict__ Wr2,
                        const float* __restrict__ b2,
                        const float* __restrict__ Wl3, const float* __restrict__ Wr3,
                        const float* __restrict__ b3,
                        float* __restrict__ out)
{
    __shared__ float sLL[8][16], sMix[8][16], sRR[8][16];
    __shared__ float sC3[8][3], sC2[8][3], sC1[8][3], sC0[8][3];
    __shared__ float sbL2[16], sbR2[16], scv[3], scu[3], scc[3];
    int t = threadIdx.x;

    if (t == 127) { g_nlist = 0; g_nlist2 = 0; }   // reset for next graph replay

    if (t < 128) {
        int i = t >> 4, j = t & 15;
        float ll = 0.f, mx = 0.f, rr = 0.f;
        #pragma unroll
        for (int k = 0; k < 16; k++) {
            float l1 = Wl1[i * 16 + k], r1 = Wr1[i * 16 + k];
            float l2 = Wl2[k * 16 + j], r2 = Wr2[k * 16 + j];
            ll += l1 * l2;
            mx += r1 * l2 + l1 * r2;
            rr += r1 * r2;
        }
        sLL[i][j] = ll; sMix[i][j] = mx; sRR[i][j] = rr;
    }
    if (t < 16) {
        float bl = 0.f, br = 0.f;
        #pragma unroll
        for (int k = 0; k < 16; k++) {
            bl += b1[k] * Wl2[k * 16 + t];
            br += b1[k] * Wr2[k * 16 + t];
        }
        sbL2[t] = bl;
        sbR2[t] = br + b2[t];
    }
    __syncthreads();

    if (t < 24) {
        int i = t / 3, cc3 = t % 3;
        float c3 = 0.f, c2 = 0.f, c1 = 0.f, c0 = 0.f;
        #pragma unroll
        for (int k = 0; k < 16; k++) {
            float l3 = Wl3[k * 3 + cc3], r3 = Wr3[k * 3 + cc3];
            c3 += sLL[i][k] * l3;
            c2 += sMix[i][k] * l3 + sLL[i][k] * r3;
            c1 += sRR[i][k] * l3 + sMix[i][k] * r3;
            c0 += sRR[i][k] * r3;
        }
        sC3[i][cc3] = c3; sC2[i][cc3] = c2; sC1[i][cc3] = c1; sC0[i][cc3] = c0;
    }
    if (t < 3) {
        float cv = 0.f, cu = 0.f, cc = 0.f;
        #pragma unroll
        for (int k = 0; k < 16; k++) {
            float l3 = Wl3[k * 3 + t], r3 = Wr3[k * 3 + t];
            cv += sbL2[k] * l3;
            cu += sbR2[k] * l3 + sbL2[k] * r3;
            cc += sbR2[k] * r3;
        }
        scv[t] = cv; scu[t] = cu; scc[t] = cc + b3[t];
    }
    __syncthreads();

    if (t < NOUT) {
        int c = g_cnt[t];
        float inv = 1.f / (float)(c > 1 ? c : 1);
        float u = (c > 0) ? 1.f : 0.f;
        float P0r[8], P1r[8], P2r[8], P3r[8];
        float4 a, b;
        a = g_P0[t * 2]; b = g_P0[t * 2 + 1];
        P0r[0] = a.x; P0r[1] = a.y; P0r[2] = a.z; P0r[3] = a.w;
        P0r[4] = b.x; P0r[5] = b.y; P0r[6] = b.z; P0r[7] = b.w;
        a = g_S1[t * 2]; b = g_S1[t * 2 + 1];   // unnormalized -> divide by cnt
        P1r[0] = a.x * inv; P1r[1] = a.y * inv; P1r[2] = a.z * inv; P1r[3] = a.w * inv;
        P1r[4] = b.x * inv; P1r[5] = b.y * inv; P1r[6] = b.z * inv; P1r[7] = b.w * inv;
        a = g_S2[t * 2]; b = g_S2[t * 2 + 1];
        P2r[0] = a.x * inv; P2r[1] = a.y * inv; P2r[2] = a.z * inv; P2r[3] = a.w * inv;
        P2r[4] = b.x * inv; P2r[5] = b.y * inv; P2r[6] = b.z * inv; P2r[7] = b.w * inv;
        #pragma unroll
        for (int k = 0; k < 8; k++) P3r[k] = g_S3[t * 12 + k] * inv;
        float v = g_S3[t * 12 + 8] * inv;

        #pragma unroll
        for (int cc3 = 0; cc3 < 3; cc3++) {
            float acc = scc[cc3] + u * scu[cc3] + v * scv[cc3];
            #pragma unroll
            for (int k = 0; k < 8; k++) {
                acc += P3r[k] * sC3[k][cc3]
                     + P2r[k] * sC2[k][cc3]
                     + P1r[k] * sC1[k][cc3]
                     + P0r[k] * sC0[k][cc3];
            }
            out[t * 3 + cc3] = acc;
        }
    }
}

// ---------------- launch ----------------
extern "C" void kernel_launch(void* const* d_in, const int* in_sizes, int n_in,
                              void* d_out, int out_size)
{
    const float* x    = (const float*)d_in[0];
    const int*   ei   = (const int*)  d_in[1];
    const float* wpos = (const float*)d_in[2];
    const float* bpos = (const float*)d_in[3];
    const float* Wl1  = (const float*)d_in[4];
    const float* Wr1  = (const float*)d_in[5];
    const float* b1   = (const float*)d_in[6];
    const float* Wl2  = (const float*)d_in[7];
    const float* Wr2  = (const float*)d_in[8];
    const float* b2   = (const float*)d_in[9];
    const float* Wl3  = (const float*)d_in[10];
    const float* Wr3  = (const float*)d_in[11];
    const float* b3   = (const float*)d_in[12];

    int n = in_sizes[0] / 3;
    int e = in_sizes[1] / 2;
    if (n > NPAD) n = NPAD;   // scratch capacity guard (problem-fixed N=150000)
    if (e > EE)   e = EE;

    int nb = (n + 255) / 256;
    int et = (e + EPT - 1) / EPT;
    int eb = (et + 255) / 256;
    int gb = (eb > nb) ? eb : nb;     // merged kernel covers init rows + edge chunks

    k_init_scan1 <<<gb, 256>>>(x, wpos, bpos, ei, ei + e, n, e);
    k_mark2      <<<32, 256>>>();
    k_scan2      <<<eb, 256>>>(ei, ei + e, e);
    k_mark1      <<<32, 256>>>();
    k_scan3      <<<eb, 256>>>(ei, ei + e, e);
    k_agg2       <<<64, 256>>>();
    k_small      <<<64, 256>>>();
    k_final      <<<1, 128>>>(Wl1, Wr1, b1, Wl2, Wr2, b2, Wl3, Wr3, b3, (float*)d_out);
}